// round 15
// baseline (speedup 1.0000x reference)
#include <cuda_runtime.h>

#define NU 96
#define IMG 32
#define SHAPE 3072                 // NU*IMG
#define NUNITS 9216                // NU*NU
#define NELEM (SHAPE * SHAPE)
#define NBLK (NUNITS / 2)          // 4608 blocks, 2 tiles each

// Scratch (no allocations). g_zmin zero-init = identity for inverted-key max;
// tail resets it each launch -> stateless across graph replays.
__device__ unsigned long long g_zmin[NU];   // per-ui inverted best key
__device__ float g_fm[NUNITS];
__device__ float g_va[NUNITS];
__device__ unsigned g_count;

// ---------------------------------------------------------------------------
// k_z: one 128-thread block per PAIR of adjacent tiles. 8 front-batched
// LDG.128 per thread. Block best key -> inverted atomicMax into g_zmin[ui].
// Last-block tail: 96-key argmin, BMU scalars, full fm/va tables, radius/lr
// outputs, scratch reset. Under PDL the tail overlaps k_update's load wave.
// ---------------------------------------------------------------------------
__global__ void __launch_bounds__(128) k_z(const float* __restrict__ som,
                                           const float* __restrict__ var,
                                           const float* __restrict__ x,
                                           const float* __restrict__ radius,
                                           const float* __restrict__ lr,
                                           const float* __restrict__ bmu_count,
                                           float* __restrict__ out_rad,
                                           float* __restrict__ out_lr) {
    const int u0 = blockIdx.x * 2;        // even unit; u1 = u0+1 same ui
    const int ui = u0 / NU, uj0 = u0 - ui * NU;
    const int t = threadIdx.x;
    const int rowA = t >> 3;              // 0..15
    const int col  = (t & 7) * 4;         // float4 column

    const float* sb = som + (size_t)ui * IMG * SHAPE + uj0 * IMG;
    const float* vb = var + (size_t)ui * IMG * SHAPE + uj0 * IMG;

    const size_t oA = (size_t)rowA * SHAPE + col;
    const size_t oB = (size_t)(rowA + 16) * SHAPE + col;

    // 8 independent som/var loads batched up front (tiles 0 and 1)
    float4 sa0 = *(const float4*)(sb + oA);
    float4 sb0 = *(const float4*)(sb + oB);
    float4 sa1 = *(const float4*)(sb + oA + IMG);
    float4 sb1 = *(const float4*)(sb + oB + IMG);
    float4 va0 = *(const float4*)(vb + oA);
    float4 vb0 = *(const float4*)(vb + oB);
    float4 va1 = *(const float4*)(vb + oA + IMG);
    float4 vb1 = *(const float4*)(vb + oB + IMG);
    float4 x0 = *(const float4*)(x + rowA * IMG + col);
    float4 x1 = *(const float4*)(x + (rowA + 16) * IMG + col);

    float d;
    float acc0 = 0.0f, acc1 = 0.0f;
    d = sa0.x - x0.x; acc0 += __fdividef(d * d, va0.x);
    d = sa0.y - x0.y; acc0 += __fdividef(d * d, va0.y);
    d = sa0.z - x0.z; acc0 += __fdividef(d * d, va0.z);
    d = sa0.w - x0.w; acc0 += __fdividef(d * d, va0.w);
    d = sb0.x - x1.x; acc0 += __fdividef(d * d, vb0.x);
    d = sb0.y - x1.y; acc0 += __fdividef(d * d, vb0.y);
    d = sb0.z - x1.z; acc0 += __fdividef(d * d, vb0.z);
    d = sb0.w - x1.w; acc0 += __fdividef(d * d, vb0.w);
    d = sa1.x - x0.x; acc1 += __fdividef(d * d, va1.x);
    d = sa1.y - x0.y; acc1 += __fdividef(d * d, va1.y);
    d = sa1.z - x0.z; acc1 += __fdividef(d * d, va1.z);
    d = sa1.w - x0.w; acc1 += __fdividef(d * d, va1.w);
    d = sb1.x - x1.x; acc1 += __fdividef(d * d, vb1.x);
    d = sb1.y - x1.y; acc1 += __fdividef(d * d, vb1.y);
    d = sb1.z - x1.z; acc1 += __fdividef(d * d, vb1.z);
    d = sb1.w - x1.w; acc1 += __fdividef(d * d, vb1.w);

#pragma unroll
    for (int o = 16; o; o >>= 1) {
        acc0 += __shfl_down_sync(0xffffffffu, acc0, o);
        acc1 += __shfl_down_sync(0xffffffffu, acc1, o);
    }
    __shared__ float ws0[4], ws1[4];
    if ((t & 31) == 0) { ws0[t >> 5] = acc0; ws1[t >> 5] = acc1; }
    __syncthreads();
    if (t == 0) {
        float z0 = ws0[0] + ws0[1] + ws0[2] + ws0[3];
        float z1 = ws1[0] + ws1[1] + ws1[2] + ws1[3];
        unsigned a = __float_as_uint(z0);
        a = (a & 0x80000000u) ? ~a : (a | 0x80000000u);   // orderable bits
        unsigned b = __float_as_uint(z1);
        b = (b & 0x80000000u) ? ~b : (b | 0x80000000u);
        unsigned long long k0 = ((unsigned long long)a << 32) | (unsigned)u0;
        unsigned long long k1 = ((unsigned long long)b << 32) | (unsigned)(u0 + 1);
        // inverted key: max over ~key == min over key; 0 is the identity
        atomicMax(&g_zmin[ui], ~min(k0, k1));
    }

    // ---- last-block tail ----
    __shared__ bool amLast;
    if (t == 0) {
        __threadfence();
        amLast = (atomicAdd(&g_count, 1u) == NBLK - 1);
    }
    __syncthreads();
    if (!amLast) return;
    __threadfence();

    unsigned long long inv = 0ULL;
    if (t < NU) inv = g_zmin[t];
#pragma unroll
    for (int o = 16; o; o >>= 1)
        inv = max(inv, __shfl_down_sync(0xffffffffu, inv, o));
    __shared__ unsigned long long wm[4];
    if ((t & 31) == 0) wm[t >> 5] = inv;
    __syncthreads();

    __shared__ float sp[5];
    __shared__ int sbmu;
    __shared__ float snr, snl;
    if (t == 0) {
        inv = max(max(wm[0], wm[1]), max(wm[2], wm[3]));
        unsigned long long best = ~inv;
        int bmu = (int)(best & 0xFFFFFFFFULL);
        float r   = radius[bmu];
        float lrb = lr[bmu];
        float dm  = 1.0f / (2.0f * r * r);
        sp[0] = (float)(bmu / NU);
        sp[1] = (float)(bmu % NU);
        sp[2] = r;
        sp[3] = dm;
        sp[4] = -logf(1e-7f / lrb) / dm;
        sbmu = bmu;
        float c = bmu_count[bmu * 10];
        snr = expf(-c / 15.0f);
        snl = expf(-c / 25.0f);
        g_count = 0;                        // reset for next graph replay
    }
    __syncthreads();
    const float bi = sp[0], bj = sp[1], r = sp[2], dm = sp[3], cst = sp[4];
    const int bmu = sbmu;
    const float nr = snr, nl = snl;

    // fm/va tables + radius/lr outputs (overlaps k_update's load preamble)
#pragma unroll 4
    for (int k = 0; k < NUNITS / 128; k++) {
        int e = t + k * 128;
        int i = e / NU, jj = e - i * NU;
        float di = (float)i - bi;
        float dj = (float)jj - bj;
        float cart = sqrtf(di * di + dj * dj);
        float mod = (cart > r) ? 0.0f : cart;
        g_fm[e] = lr[e] * expf(-mod) * dm;
        float sig = 1.0f / (1.0f + expf(-cart / cst));
        g_va[e] = fminf(fmaxf(0.4f + sig, 0.0f), 1.0f);   // ALPHA-0.5 = 0.4
        out_rad[e] = fmaxf((e == bmu) ? nr : radius[e], 1e-5f);
        out_lr[e]  = fmaxf((e == bmu) ? nl : lr[e], 1e-5f);
    }
    if (t < NU) g_zmin[t] = 0ULL;           // reset identity
    __threadfence();
}

// ---------------------------------------------------------------------------
// k_update (PDL secondary): pure streaming. 10 batched loads -> griddepsync
// -> 4 scalar table loads -> FMA chain -> 4 streaming stores. No MUFU work.
// ---------------------------------------------------------------------------
__global__ void __launch_bounds__(128) k_update(const float* __restrict__ som,
                                                const float* __restrict__ var,
                                                const float* __restrict__ x,
                                                float* __restrict__ out_som,
                                                float* __restrict__ out_var) {
    const int u0 = blockIdx.x * 2;
    const int ui = u0 / NU, uj0 = u0 - ui * NU;
    const int t = threadIdx.x;

    const int rowA = t >> 3;
    const int col  = (t & 7) * 4;
    const size_t base = (size_t)ui * IMG * SHAPE + uj0 * IMG;
    const size_t oA = base + (size_t)rowA * SHAPE + col;
    const size_t oB = base + (size_t)(rowA + 16) * SHAPE + col;

    // ---- preamble: all loads independent of the argmin ----
    float4 sa0 = __ldlu((const float4*)(som + oA));
    float4 sb0 = __ldlu((const float4*)(som + oB));
    float4 sa1 = __ldlu((const float4*)(som + oA + IMG));
    float4 sb1 = __ldlu((const float4*)(som + oB + IMG));
    float4 va0 = __ldlu((const float4*)(var + oA));
    float4 vb0 = __ldlu((const float4*)(var + oB));
    float4 va1 = __ldlu((const float4*)(var + oA + IMG));
    float4 vb1 = __ldlu((const float4*)(var + oB + IMG));
    float4 x0 = *(const float4*)(x + rowA * IMG + col);
    float4 x1 = *(const float4*)(x + (rowA + 16) * IMG + col);

    // ---- wait for k_z grid (fm/va tables now visible) ----
    cudaGridDependencySynchronize();

    const float fm0 = g_fm[u0];
    const float fm1 = g_fm[u0 + 1];
    const float vaA = g_va[u0];
    const float vaB = g_va[u0 + 1];
    const float ivA = 1.0f - vaA, ivB = 1.0f - vaB;

    float4 os, ov;
#define UPD1(S, X, V, FM, VA, IVA, OS, OV)                     \
    {                                                          \
        float ns = S + FM * (X - S);                           \
        float dd = X - ns;                                     \
        OV = VA * V + IVA * dd * dd;                           \
        OS = fminf(fmaxf(ns, 0.0f), 1.0f);                     \
    }
#define UPD4(SV, XV, VV, FM, VA, IVA, OUTS, OUTV, OFF)         \
    UPD1(SV.x, XV.x, VV.x, FM, VA, IVA, os.x, ov.x)            \
    UPD1(SV.y, XV.y, VV.y, FM, VA, IVA, os.y, ov.y)            \
    UPD1(SV.z, XV.z, VV.z, FM, VA, IVA, os.z, ov.z)            \
    UPD1(SV.w, XV.w, VV.w, FM, VA, IVA, os.w, ov.w)            \
    __stcs((float4*)(OUTS + OFF), os);                         \
    __stcs((float4*)(OUTV + OFF), ov);

    UPD4(sa0, x0, va0, fm0, vaA, ivA, out_som, out_var, oA)
    UPD4(sb0, x1, vb0, fm0, vaA, ivA, out_som, out_var, oB)
    UPD4(sa1, x0, va1, fm1, vaB, ivB, out_som, out_var, oA + IMG)
    UPD4(sb1, x1, vb1, fm1, vaB, ivB, out_som, out_var, oB + IMG)
#undef UPD4
#undef UPD1
}

extern "C" void kernel_launch(void* const* d_in, const int* in_sizes, int n_in,
                              void* d_out, int out_size) {
    const float* x      = (const float*)d_in[0];
    const float* som    = (const float*)d_in[1];
    const float* var    = (const float*)d_in[2];
    const float* radius = (const float*)d_in[3];
    const float* lr     = (const float*)d_in[4];
    const float* bmu    = (const float*)d_in[5];

    float* out      = (float*)d_out;
    float* out_som  = out;
    float* out_var  = out + (size_t)NELEM;
    float* out_rad  = out + 2ULL * NELEM;
    float* out_lr   = out + 2ULL * NELEM + NUNITS;

    k_z<<<NBLK, 128>>>(som, var, x, radius, lr, bmu, out_rad, out_lr);

    // PDL secondary: launch overlaps k_z's drain; ordering enforced in-kernel
    // by cudaGridDependencySynchronize().
    cudaLaunchConfig_t cfg = {};
    cfg.gridDim = dim3(NBLK);
    cfg.blockDim = dim3(128);
    cfg.dynamicSmemBytes = 0;
    cfg.stream = 0;
    cudaLaunchAttribute attr[1];
    attr[0].id = cudaLaunchAttributeProgrammaticStreamSerialization;
    attr[0].val.programmaticStreamSerializationAllowed = 1;
    cfg.attrs = attr;
    cfg.numAttrs = 1;
    cudaLaunchKernelEx(&cfg, k_update, som, var, x, out_som, out_var);
}

// round 16
// speedup vs baseline: 2.3858x; 2.3858x over previous
#include <cuda_runtime.h>

#define NU 96
#define IMG 32
#define SHAPE 3072                 // NU*IMG
#define NUNITS 9216                // NU*NU
#define NELEM (SHAPE * SHAPE)
#define NBLK (NUNITS / 2)          // 4608 blocks, 2 tiles each

// Scratch (no allocations). g_zmin zero-init = identity for inverted-key max;
// tail resets it each launch -> stateless across graph replays.
__device__ unsigned long long g_zmin[NU];   // per-ui inverted best key
__device__ float g_params[5];               // bi, bj, r, dm, constant
__device__ int   g_bmu;
__device__ unsigned g_count;

// ---------------------------------------------------------------------------
// k_z: one 128-thread block per PAIR of adjacent tiles. 8 front-batched
// LDG.128 per thread. Block best key -> inverted atomicMax into g_zmin[ui].
// Tiny last-block tail: reduce 96 keys, BMU scalars, reset scratch.
// ---------------------------------------------------------------------------
__global__ void __launch_bounds__(128) k_z(const float* __restrict__ som,
                                           const float* __restrict__ var,
                                           const float* __restrict__ x,
                                           const float* __restrict__ radius,
                                           const float* __restrict__ lr) {
    const int u0 = blockIdx.x * 2;        // even unit; u1 = u0+1 same ui
    const int ui = u0 / NU, uj0 = u0 - ui * NU;
    const int t = threadIdx.x;
    const int rowA = t >> 3;              // 0..15
    const int col  = (t & 7) * 4;         // float4 column

    const float* sb = som + (size_t)ui * IMG * SHAPE + uj0 * IMG;
    const float* vb = var + (size_t)ui * IMG * SHAPE + uj0 * IMG;

    const size_t oA = (size_t)rowA * SHAPE + col;
    const size_t oB = (size_t)(rowA + 16) * SHAPE + col;

    // 8 independent som/var loads batched up front (tiles 0 and 1)
    float4 sa0 = *(const float4*)(sb + oA);
    float4 sb0 = *(const float4*)(sb + oB);
    float4 sa1 = *(const float4*)(sb + oA + IMG);
    float4 sb1 = *(const float4*)(sb + oB + IMG);
    float4 va0 = *(const float4*)(vb + oA);
    float4 vb0 = *(const float4*)(vb + oB);
    float4 va1 = *(const float4*)(vb + oA + IMG);
    float4 vb1 = *(const float4*)(vb + oB + IMG);
    float4 x0 = *(const float4*)(x + rowA * IMG + col);
    float4 x1 = *(const float4*)(x + (rowA + 16) * IMG + col);

    float d;
    float acc0 = 0.0f, acc1 = 0.0f;
    d = sa0.x - x0.x; acc0 += __fdividef(d * d, va0.x);
    d = sa0.y - x0.y; acc0 += __fdividef(d * d, va0.y);
    d = sa0.z - x0.z; acc0 += __fdividef(d * d, va0.z);
    d = sa0.w - x0.w; acc0 += __fdividef(d * d, va0.w);
    d = sb0.x - x1.x; acc0 += __fdividef(d * d, vb0.x);
    d = sb0.y - x1.y; acc0 += __fdividef(d * d, vb0.y);
    d = sb0.z - x1.z; acc0 += __fdividef(d * d, vb0.z);
    d = sb0.w - x1.w; acc0 += __fdividef(d * d, vb0.w);
    d = sa1.x - x0.x; acc1 += __fdividef(d * d, va1.x);
    d = sa1.y - x0.y; acc1 += __fdividef(d * d, va1.y);
    d = sa1.z - x0.z; acc1 += __fdividef(d * d, va1.z);
    d = sa1.w - x0.w; acc1 += __fdividef(d * d, va1.w);
    d = sb1.x - x1.x; acc1 += __fdividef(d * d, vb1.x);
    d = sb1.y - x1.y; acc1 += __fdividef(d * d, vb1.y);
    d = sb1.z - x1.z; acc1 += __fdividef(d * d, vb1.z);
    d = sb1.w - x1.w; acc1 += __fdividef(d * d, vb1.w);

#pragma unroll
    for (int o = 16; o; o >>= 1) {
        acc0 += __shfl_down_sync(0xffffffffu, acc0, o);
        acc1 += __shfl_down_sync(0xffffffffu, acc1, o);
    }
    __shared__ float ws0[4], ws1[4];
    if ((t & 31) == 0) { ws0[t >> 5] = acc0; ws1[t >> 5] = acc1; }
    __syncthreads();
    if (t == 0) {
        float z0 = ws0[0] + ws0[1] + ws0[2] + ws0[3];
        float z1 = ws1[0] + ws1[1] + ws1[2] + ws1[3];
        unsigned a = __float_as_uint(z0);
        a = (a & 0x80000000u) ? ~a : (a | 0x80000000u);   // orderable bits
        unsigned b = __float_as_uint(z1);
        b = (b & 0x80000000u) ? ~b : (b | 0x80000000u);
        unsigned long long k0 = ((unsigned long long)a << 32) | (unsigned)u0;
        unsigned long long k1 = ((unsigned long long)b << 32) | (unsigned)(u0 + 1);
        // inverted key: max over ~key == min over key; 0 is the identity
        atomicMax(&g_zmin[ui], ~min(k0, k1));
    }

    // ---- tiny last-block tail: 96-key reduce + BMU scalars + reset ----
    __shared__ bool amLast;
    if (t == 0) {
        __threadfence();
        amLast = (atomicAdd(&g_count, 1u) == NBLK - 1);
    }
    __syncthreads();
    if (!amLast) return;
    __threadfence();

    unsigned long long inv = 0ULL;
    if (t < NU) inv = g_zmin[t];
#pragma unroll
    for (int o = 16; o; o >>= 1)
        inv = max(inv, __shfl_down_sync(0xffffffffu, inv, o));
    __shared__ unsigned long long wm[4];
    if ((t & 31) == 0) wm[t >> 5] = inv;
    __syncthreads();
    if (t == 0) {
        inv = max(max(wm[0], wm[1]), max(wm[2], wm[3]));
        unsigned long long best = ~inv;
        int bmu = (int)(best & 0xFFFFFFFFULL);
        float r   = radius[bmu];
        float lrb = lr[bmu];
        float dm  = 1.0f / (2.0f * r * r);
        g_params[0] = (float)(bmu / NU);
        g_params[1] = (float)(bmu % NU);
        g_params[2] = r;
        g_params[3] = dm;
        g_params[4] = -logf(1e-7f / lrb) / dm;
        g_bmu = bmu;
        g_count = 0;                        // reset for next graph replay
    }
    if (t < NU) g_zmin[t] = 0ULL;           // reset identity
    if (t == 0) __threadfence();
}

// ---------------------------------------------------------------------------
// k_update (PDL secondary): REVERSE unit order — consumes the L2-hot tail of
// som/var (most recently read by k_z) first, walking backwards along the
// eviction frontier. Loads batched before griddepsync.
// ---------------------------------------------------------------------------
__global__ void __launch_bounds__(128) k_update(const float* __restrict__ som,
                                                const float* __restrict__ var,
                                                const float* __restrict__ x,
                                                const float* __restrict__ lr,
                                                const float* __restrict__ radius,
                                                const float* __restrict__ bmu_count,
                                                float* __restrict__ out_som,
                                                float* __restrict__ out_var,
                                                float* __restrict__ out_rad,
                                                float* __restrict__ out_lr) {
    const int u0 = (NUNITS - 2) - blockIdx.x * 2;   // reverse traversal
    const int ui = u0 / NU, uj0 = u0 - ui * NU;
    const int t = threadIdx.x;

    const int rowA = t >> 3;
    const int col  = (t & 7) * 4;
    const size_t base = (size_t)ui * IMG * SHAPE + uj0 * IMG;
    const size_t oA = base + (size_t)rowA * SHAPE + col;
    const size_t oB = base + (size_t)(rowA + 16) * SHAPE + col;

    // ---- preamble: every load that does NOT depend on the argmin ----
    float4 sa0 = __ldlu((const float4*)(som + oA));
    float4 sb0 = __ldlu((const float4*)(som + oB));
    float4 sa1 = __ldlu((const float4*)(som + oA + IMG));
    float4 sb1 = __ldlu((const float4*)(som + oB + IMG));
    float4 va0 = __ldlu((const float4*)(var + oA));
    float4 vb0 = __ldlu((const float4*)(var + oB));
    float4 va1 = __ldlu((const float4*)(var + oA + IMG));
    float4 vb1 = __ldlu((const float4*)(var + oB + IMG));
    float4 x0 = *(const float4*)(x + rowA * IMG + col);
    float4 x1 = *(const float4*)(x + (rowA + 16) * IMG + col);
    float lr0 = lr[u0];
    float lr1 = lr[u0 + 1];

    // ---- wait for k_z grid (params + bmu now visible) ----
    cudaGridDependencySynchronize();

    const float bi = g_params[0], bj = g_params[1];
    const float r = g_params[2], dm = g_params[3], cst = g_params[4];
    const int bmu = g_bmu;

    // Side job: radius / learning-rate outputs (blocks 0..71)
    if (blockIdx.x < NUNITS / 128) {
        int e = blockIdx.x * 128 + t;
        float c  = bmu_count[bmu * 10];
        float nr = expf(-c / 15.0f);
        float nl = expf(-c / 25.0f);
        out_rad[e] = fmaxf((e == bmu) ? nr : radius[e], 1e-5f);
        out_lr[e]  = fmaxf((e == bmu) ? nl : lr[e], 1e-5f);
    }

    // Per-tile scalars (redundant per thread)
    const float di = (float)ui - bi;
    const float dj0 = (float)uj0 - bj;
    const float dj1 = (float)(uj0 + 1) - bj;
    float cart0 = sqrtf(di * di + dj0 * dj0);
    float cart1 = sqrtf(di * di + dj1 * dj1);
    float fm0 = lr0 * expf(-((cart0 > r) ? 0.0f : cart0)) * dm;
    float fm1 = lr1 * expf(-((cart1 > r) ? 0.0f : cart1)) * dm;
    float vaA = fminf(fmaxf(0.4f + 1.0f / (1.0f + expf(-cart0 / cst)), 0.0f), 1.0f);
    float vaB = fminf(fmaxf(0.4f + 1.0f / (1.0f + expf(-cart1 / cst)), 0.0f), 1.0f);
    float ivA = 1.0f - vaA, ivB = 1.0f - vaB;

    float4 os, ov;
#define UPD1(S, X, V, FM, VA, IVA, OS, OV)                     \
    {                                                          \
        float ns = S + FM * (X - S);                           \
        float dd = X - ns;                                     \
        OV = VA * V + IVA * dd * dd;                           \
        OS = fminf(fmaxf(ns, 0.0f), 1.0f);                     \
    }
#define UPD4(SV, XV, VV, FM, VA, IVA, OUTS, OUTV, OFF)         \
    UPD1(SV.x, XV.x, VV.x, FM, VA, IVA, os.x, ov.x)            \
    UPD1(SV.y, XV.y, VV.y, FM, VA, IVA, os.y, ov.y)            \
    UPD1(SV.z, XV.z, VV.z, FM, VA, IVA, os.z, ov.z)            \
    UPD1(SV.w, XV.w, VV.w, FM, VA, IVA, os.w, ov.w)            \
    __stcs((float4*)(OUTS + OFF), os);                         \
    __stcs((float4*)(OUTV + OFF), ov);

    UPD4(sa0, x0, va0, fm0, vaA, ivA, out_som, out_var, oA)
    UPD4(sb0, x1, vb0, fm0, vaA, ivA, out_som, out_var, oB)
    UPD4(sa1, x0, va1, fm1, vaB, ivB, out_som, out_var, oA + IMG)
    UPD4(sb1, x1, vb1, fm1, vaB, ivB, out_som, out_var, oB + IMG)
#undef UPD4
#undef UPD1
}

extern "C" void kernel_launch(void* const* d_in, const int* in_sizes, int n_in,
                              void* d_out, int out_size) {
    const float* x      = (const float*)d_in[0];
    const float* som    = (const float*)d_in[1];
    const float* var    = (const float*)d_in[2];
    const float* radius = (const float*)d_in[3];
    const float* lr     = (const float*)d_in[4];
    const float* bmu    = (const float*)d_in[5];

    float* out      = (float*)d_out;
    float* out_som  = out;
    float* out_var  = out + (size_t)NELEM;
    float* out_rad  = out + 2ULL * NELEM;
    float* out_lr   = out + 2ULL * NELEM + NUNITS;

    k_z<<<NBLK, 128>>>(som, var, x, radius, lr);

    // PDL secondary: may begin launching while k_z drains; ordering enforced
    // in-kernel by cudaGridDependencySynchronize().
    cudaLaunchConfig_t cfg = {};
    cfg.gridDim = dim3(NBLK);
    cfg.blockDim = dim3(128);
    cfg.dynamicSmemBytes = 0;
    cfg.stream = 0;                        // same (capture) stream as <<<>>>
    cudaLaunchAttribute attr[1];
    attr[0].id = cudaLaunchAttributeProgrammaticStreamSerialization;
    attr[0].val.programmaticStreamSerializationAllowed = 1;
    cfg.attrs = attr;
    cfg.numAttrs = 1;
    cudaLaunchKernelEx(&cfg, k_update, som, var, x, lr, radius, bmu,
                       out_som, out_var, out_rad, out_lr);
}

// round 17
// speedup vs baseline: 2.9067x; 1.2183x over previous
#include <cuda_runtime.h>

#define NU 96
#define IMG 32
#define SHAPE 3072                 // NU*IMG
#define NUNITS 9216                // NU*NU
#define NELEM (SHAPE * SHAPE)
#define NBLK (NUNITS / 2)          // 4608 blocks, 2 tiles each

// Scratch (no allocations). g_zmin zero-init = identity for inverted-key max;
// tail resets it each launch -> stateless across graph replays.
__device__ unsigned long long g_zmin[NU];   // per-ui inverted best key
__device__ float g_params[5];               // bi, bj, r, dm, constant
__device__ int   g_bmu;
__device__ unsigned g_count;

// ---------------------------------------------------------------------------
// k_z: one 128-thread block per PAIR of adjacent tiles. 8 front-batched
// LDG.128 per thread. Block best key -> inverted atomicMax into g_zmin[ui].
// Tiny last-block tail: reduce 96 keys, BMU scalars, reset scratch.
// ---------------------------------------------------------------------------
__global__ void __launch_bounds__(128) k_z(const float* __restrict__ som,
                                           const float* __restrict__ var,
                                           const float* __restrict__ x,
                                           const float* __restrict__ radius,
                                           const float* __restrict__ lr) {
    const int u0 = blockIdx.x * 2;        // even unit; u1 = u0+1 same ui
    const int ui = u0 / NU, uj0 = u0 - ui * NU;
    const int t = threadIdx.x;
    const int rowA = t >> 3;              // 0..15
    const int col  = (t & 7) * 4;         // float4 column

    const float* sb = som + (size_t)ui * IMG * SHAPE + uj0 * IMG;
    const float* vb = var + (size_t)ui * IMG * SHAPE + uj0 * IMG;

    const size_t oA = (size_t)rowA * SHAPE + col;
    const size_t oB = (size_t)(rowA + 16) * SHAPE + col;

    // 8 independent som/var loads batched up front (tiles 0 and 1)
    float4 sa0 = *(const float4*)(sb + oA);
    float4 sb0 = *(const float4*)(sb + oB);
    float4 sa1 = *(const float4*)(sb + oA + IMG);
    float4 sb1 = *(const float4*)(sb + oB + IMG);
    float4 va0 = *(const float4*)(vb + oA);
    float4 vb0 = *(const float4*)(vb + oB);
    float4 va1 = *(const float4*)(vb + oA + IMG);
    float4 vb1 = *(const float4*)(vb + oB + IMG);
    float4 x0 = *(const float4*)(x + rowA * IMG + col);
    float4 x1 = *(const float4*)(x + (rowA + 16) * IMG + col);

    float d;
    float acc0 = 0.0f, acc1 = 0.0f;
    d = sa0.x - x0.x; acc0 += __fdividef(d * d, va0.x);
    d = sa0.y - x0.y; acc0 += __fdividef(d * d, va0.y);
    d = sa0.z - x0.z; acc0 += __fdividef(d * d, va0.z);
    d = sa0.w - x0.w; acc0 += __fdividef(d * d, va0.w);
    d = sb0.x - x1.x; acc0 += __fdividef(d * d, vb0.x);
    d = sb0.y - x1.y; acc0 += __fdividef(d * d, vb0.y);
    d = sb0.z - x1.z; acc0 += __fdividef(d * d, vb0.z);
    d = sb0.w - x1.w; acc0 += __fdividef(d * d, vb0.w);
    d = sa1.x - x0.x; acc1 += __fdividef(d * d, va1.x);
    d = sa1.y - x0.y; acc1 += __fdividef(d * d, va1.y);
    d = sa1.z - x0.z; acc1 += __fdividef(d * d, va1.z);
    d = sa1.w - x0.w; acc1 += __fdividef(d * d, va1.w);
    d = sb1.x - x1.x; acc1 += __fdividef(d * d, vb1.x);
    d = sb1.y - x1.y; acc1 += __fdividef(d * d, vb1.y);
    d = sb1.z - x1.z; acc1 += __fdividef(d * d, vb1.z);
    d = sb1.w - x1.w; acc1 += __fdividef(d * d, vb1.w);

#pragma unroll
    for (int o = 16; o; o >>= 1) {
        acc0 += __shfl_down_sync(0xffffffffu, acc0, o);
        acc1 += __shfl_down_sync(0xffffffffu, acc1, o);
    }
    __shared__ float ws0[4], ws1[4];
    if ((t & 31) == 0) { ws0[t >> 5] = acc0; ws1[t >> 5] = acc1; }
    __syncthreads();
    if (t == 0) {
        float z0 = ws0[0] + ws0[1] + ws0[2] + ws0[3];
        float z1 = ws1[0] + ws1[1] + ws1[2] + ws1[3];
        unsigned a = __float_as_uint(z0);
        a = (a & 0x80000000u) ? ~a : (a | 0x80000000u);   // orderable bits
        unsigned b = __float_as_uint(z1);
        b = (b & 0x80000000u) ? ~b : (b | 0x80000000u);
        unsigned long long k0 = ((unsigned long long)a << 32) | (unsigned)u0;
        unsigned long long k1 = ((unsigned long long)b << 32) | (unsigned)(u0 + 1);
        // inverted key: max over ~key == min over key; 0 is the identity
        atomicMax(&g_zmin[ui], ~min(k0, k1));
    }

    // ---- tiny last-block tail: 96-key reduce + BMU scalars + reset ----
    __shared__ bool amLast;
    if (t == 0) {
        __threadfence();
        amLast = (atomicAdd(&g_count, 1u) == NBLK - 1);
    }
    __syncthreads();
    if (!amLast) return;
    __threadfence();

    unsigned long long inv = 0ULL;
    if (t < NU) inv = g_zmin[t];
#pragma unroll
    for (int o = 16; o; o >>= 1)
        inv = max(inv, __shfl_down_sync(0xffffffffu, inv, o));
    __shared__ unsigned long long wm[4];
    if ((t & 31) == 0) wm[t >> 5] = inv;
    __syncthreads();
    if (t == 0) {
        inv = max(max(wm[0], wm[1]), max(wm[2], wm[3]));
        unsigned long long best = ~inv;
        int bmu = (int)(best & 0xFFFFFFFFULL);
        float r   = radius[bmu];
        float lrb = lr[bmu];
        float dm  = 1.0f / (2.0f * r * r);
        g_params[0] = (float)(bmu / NU);
        g_params[1] = (float)(bmu % NU);
        g_params[2] = r;
        g_params[3] = dm;
        g_params[4] = -logf(1e-7f / lrb) / dm;
        g_bmu = bmu;
        g_count = 0;                        // reset for next graph replay
    }
    if (t < NU) g_zmin[t] = 0ULL;           // reset identity
    if (t == 0) __threadfence();
}

// ---------------------------------------------------------------------------
// k_update (PDL secondary): forward unit order (matches k_z's L2 footprint).
// All argmin-independent loads issued before cudaGridDependencySynchronize().
// ---------------------------------------------------------------------------
__global__ void __launch_bounds__(128) k_update(const float* __restrict__ som,
                                                const float* __restrict__ var,
                                                const float* __restrict__ x,
                                                const float* __restrict__ lr,
                                                const float* __restrict__ radius,
                                                const float* __restrict__ bmu_count,
                                                float* __restrict__ out_som,
                                                float* __restrict__ out_var,
                                                float* __restrict__ out_rad,
                                                float* __restrict__ out_lr) {
    const int u0 = blockIdx.x * 2;
    const int ui = u0 / NU, uj0 = u0 - ui * NU;
    const int t = threadIdx.x;

    const int rowA = t >> 3;
    const int col  = (t & 7) * 4;
    const size_t base = (size_t)ui * IMG * SHAPE + uj0 * IMG;
    const size_t oA = base + (size_t)rowA * SHAPE + col;
    const size_t oB = base + (size_t)(rowA + 16) * SHAPE + col;

    // ---- preamble: every load that does NOT depend on the argmin ----
    float4 sa0 = __ldlu((const float4*)(som + oA));
    float4 sb0 = __ldlu((const float4*)(som + oB));
    float4 sa1 = __ldlu((const float4*)(som + oA + IMG));
    float4 sb1 = __ldlu((const float4*)(som + oB + IMG));
    float4 va0 = __ldlu((const float4*)(var + oA));
    float4 vb0 = __ldlu((const float4*)(var + oB));
    float4 va1 = __ldlu((const float4*)(var + oA + IMG));
    float4 vb1 = __ldlu((const float4*)(var + oB + IMG));
    float4 x0 = *(const float4*)(x + rowA * IMG + col);
    float4 x1 = *(const float4*)(x + (rowA + 16) * IMG + col);
    float lr0 = lr[u0];
    float lr1 = lr[u0 + 1];

    // ---- wait for k_z grid (params + bmu now visible) ----
    cudaGridDependencySynchronize();

    const float bi = g_params[0], bj = g_params[1];
    const float r = g_params[2], dm = g_params[3], cst = g_params[4];
    const int bmu = g_bmu;

    // Side job: radius / learning-rate outputs (blocks 0..71)
    if (blockIdx.x < NUNITS / 128) {
        int e = blockIdx.x * 128 + t;
        float c  = bmu_count[bmu * 10];
        float nr = expf(-c / 15.0f);
        float nl = expf(-c / 25.0f);
        out_rad[e] = fmaxf((e == bmu) ? nr : radius[e], 1e-5f);
        out_lr[e]  = fmaxf((e == bmu) ? nl : lr[e], 1e-5f);
    }

    // Per-tile scalars (redundant per thread)
    const float di = (float)ui - bi;
    const float dj0 = (float)uj0 - bj;
    const float dj1 = (float)(uj0 + 1) - bj;
    float cart0 = sqrtf(di * di + dj0 * dj0);
    float cart1 = sqrtf(di * di + dj1 * dj1);
    float fm0 = lr0 * expf(-((cart0 > r) ? 0.0f : cart0)) * dm;
    float fm1 = lr1 * expf(-((cart1 > r) ? 0.0f : cart1)) * dm;
    float vaA = fminf(fmaxf(0.4f + 1.0f / (1.0f + expf(-cart0 / cst)), 0.0f), 1.0f);
    float vaB = fminf(fmaxf(0.4f + 1.0f / (1.0f + expf(-cart1 / cst)), 0.0f), 1.0f);
    float ivA = 1.0f - vaA, ivB = 1.0f - vaB;

    float4 os, ov;
#define UPD1(S, X, V, FM, VA, IVA, OS, OV)                     \
    {                                                          \
        float ns = S + FM * (X - S);                           \
        float dd = X - ns;                                     \
        OV = VA * V + IVA * dd * dd;                           \
        OS = fminf(fmaxf(ns, 0.0f), 1.0f);                     \
    }
#define UPD4(SV, XV, VV, FM, VA, IVA, OUTS, OUTV, OFF)         \
    UPD1(SV.x, XV.x, VV.x, FM, VA, IVA, os.x, ov.x)            \
    UPD1(SV.y, XV.y, VV.y, FM, VA, IVA, os.y, ov.y)            \
    UPD1(SV.z, XV.z, VV.z, FM, VA, IVA, os.z, ov.z)            \
    UPD1(SV.w, XV.w, VV.w, FM, VA, IVA, os.w, ov.w)            \
    __stcs((float4*)(OUTS + OFF), os);                         \
    __stcs((float4*)(OUTV + OFF), ov);

    UPD4(sa0, x0, va0, fm0, vaA, ivA, out_som, out_var, oA)
    UPD4(sb0, x1, vb0, fm0, vaA, ivA, out_som, out_var, oB)
    UPD4(sa1, x0, va1, fm1, vaB, ivB, out_som, out_var, oA + IMG)
    UPD4(sb1, x1, vb1, fm1, vaB, ivB, out_som, out_var, oB + IMG)
#undef UPD4
#undef UPD1
}

extern "C" void kernel_launch(void* const* d_in, const int* in_sizes, int n_in,
                              void* d_out, int out_size) {
    const float* x      = (const float*)d_in[0];
    const float* som    = (const float*)d_in[1];
    const float* var    = (const float*)d_in[2];
    const float* radius = (const float*)d_in[3];
    const float* lr     = (const float*)d_in[4];
    const float* bmu    = (const float*)d_in[5];

    float* out      = (float*)d_out;
    float* out_som  = out;
    float* out_var  = out + (size_t)NELEM;
    float* out_rad  = out + 2ULL * NELEM;
    float* out_lr   = out + 2ULL * NELEM + NUNITS;

    k_z<<<NBLK, 128>>>(som, var, x, radius, lr);

    // PDL secondary: may begin launching while k_z drains; ordering enforced
    // in-kernel by cudaGridDependencySynchronize().
    cudaLaunchConfig_t cfg = {};
    cfg.gridDim = dim3(NBLK);
    cfg.blockDim = dim3(128);
    cfg.dynamicSmemBytes = 0;
    cfg.stream = 0;                        // same (capture) stream as <<<>>>
    cudaLaunchAttribute attr[1];
    attr[0].id = cudaLaunchAttributeProgrammaticStreamSerialization;
    attr[0].val.programmaticStreamSerializationAllowed = 1;
    cfg.attrs = attr;
    cfg.numAttrs = 1;
    cudaLaunchKernelEx(&cfg, k_update, som, var, x, lr, radius, bmu,
                       out_som, out_var, out_rad, out_lr);
}